// round 3
// baseline (speedup 1.0000x reference)
#include <cuda_runtime.h>
#include <math.h>
#include <stdint.h>

#define NB 8
#define NT 2048
#define NC 1024
#define NH 128
#define NBT (NB*NT)

__device__ float g_Q[NBT*NH];
__device__ float g_K[NBT*NH];
__device__ float g_V[NBT*NH];

// ===========================================================================
// tf32 warp MMA helpers (sm_80+ PTX — no arch-specific 'a' features)
// ===========================================================================
__device__ __forceinline__ uint32_t f2tf(float x) {
    uint32_t r;
    asm("cvt.rna.tf32.f32 %0, %1;" : "=r"(r) : "f"(x));
    return r;
}
__device__ __forceinline__ void split_tf32(float x, uint32_t& hi, uint32_t& lo) {
    hi = f2tf(x);
    lo = f2tf(x - __uint_as_float(hi));
}
__device__ __forceinline__ void mma_tf32(float* d, const uint32_t* a, const uint32_t* b) {
    asm volatile(
        "mma.sync.aligned.m16n8k8.row.col.f32.tf32.tf32.f32 "
        "{%0,%1,%2,%3}, {%4,%5,%6,%7}, {%8,%9}, {%0,%1,%2,%3};"
        : "+f"(d[0]), "+f"(d[1]), "+f"(d[2]), "+f"(d[3])
        : "r"(a[0]), "r"(a[1]), "r"(a[2]), "r"(a[3]), "r"(b[0]), "r"(b[1]));
}

// ===========================================================================
// QKV projection: out[m][n] = sum_k x[m][k] * W[n][k], via split-tf32 MMA.
// CTA: 128(M) x 128(N), K chunked by 32, double-buffered smem (pad 36).
// 8 warps: warpM = wid&3 (32 rows), warpN = wid>>2 (64 cols).
// blockIdx.y selects Wq/Wk/Wv.
// ===========================================================================
#define KC 32
#define APAD 36
#define STAGEF (2 * 128 * APAD)   // floats per stage (A tile + B tile)
#define QKV_SMEM (2 * STAGEF * 4) // bytes

__global__ __launch_bounds__(256, 1)
void qkv_mma_kernel(const float* __restrict__ x,
                    const float* __restrict__ Wq,
                    const float* __restrict__ Wk,
                    const float* __restrict__ Wv) {
    extern __shared__ float sm[];

    const float* __restrict__ W = (blockIdx.y == 0) ? Wq : (blockIdx.y == 1) ? Wk : Wv;
    float* out = (blockIdx.y == 0) ? g_Q : (blockIdx.y == 1) ? g_K : g_V;

    const int tid  = threadIdx.x;
    const int wid  = tid >> 5;
    const int lane = tid & 31;
    const int g    = lane >> 2;
    const int tig  = lane & 3;
    const int m0   = blockIdx.x * 128;

    // cooperative load mapping: 4 float4 per thread per tile
    const int r0 = tid >> 3;           // base row (step 32 per it)
    const int c4 = (tid & 7) * 4;      // col within 32-chunk
    const float* xb = x + (size_t)(m0 + r0) * NC + c4;
    const float* wb = W + (size_t)r0 * NC + c4;

    // load chunk 0 into stage 0
    {
        float* As = sm;
        float* Bs = sm + 128 * APAD;
        #pragma unroll
        for (int it = 0; it < 4; it++) {
            *(float4*)&As[(r0 + 32*it) * APAD + c4] = *(const float4*)(xb + (size_t)(32*it) * NC);
            *(float4*)&Bs[(r0 + 32*it) * APAD + c4] = *(const float4*)(wb + (size_t)(32*it) * NC);
        }
    }
    __syncthreads();

    float acc[2][8][4];
    #pragma unroll
    for (int mf = 0; mf < 2; mf++)
        #pragma unroll
        for (int nf = 0; nf < 8; nf++)
            #pragma unroll
            for (int i = 0; i < 4; i++) acc[mf][nf][i] = 0.f;

    const int mrow = (wid & 3) * 32 + g;    // + mf*16 (+8)
    const int nbase = (wid >> 2) * 64 + g;  // + nf*8

    for (int c = 0; c < NC / KC; c++) {
        const int st = c & 1;
        const float* As = sm + st * STAGEF;
        const float* Bs = As + 128 * APAD;

        float4 pa[4], pb[4];
        if (c < NC / KC - 1) {
            const int kn = (c + 1) * KC;
            #pragma unroll
            for (int it = 0; it < 4; it++) {
                pa[it] = *(const float4*)(xb + (size_t)(32*it) * NC + kn);
                pb[it] = *(const float4*)(wb + (size_t)(32*it) * NC + kn);
            }
        }

        #pragma unroll
        for (int kk = 0; kk < 4; kk++) {
            const int kc = kk * 8;
            uint32_t ahi[2][4], alo[2][4];
            #pragma unroll
            for (int mf = 0; mf < 2; mf++) {
                const int r = mrow + mf * 16;
                float v0 = As[r       * APAD + kc + tig];
                float v1 = As[(r + 8) * APAD + kc + tig];
                float v2 = As[r       * APAD + kc + tig + 4];
                float v3 = As[(r + 8) * APAD + kc + tig + 4];
                split_tf32(v0, ahi[mf][0], alo[mf][0]);
                split_tf32(v1, ahi[mf][1], alo[mf][1]);
                split_tf32(v2, ahi[mf][2], alo[mf][2]);
                split_tf32(v3, ahi[mf][3], alo[mf][3]);
            }
            #pragma unroll
            for (int nf = 0; nf < 8; nf++) {
                const int bc = nbase + nf * 8;
                float y0 = Bs[bc * APAD + kc + tig];
                float y1 = Bs[bc * APAD + kc + tig + 4];
                uint32_t bh[2], bl[2];
                split_tf32(y0, bh[0], bl[0]);
                split_tf32(y1, bh[1], bl[1]);
                #pragma unroll
                for (int mf = 0; mf < 2; mf++) {
                    mma_tf32(acc[mf][nf], ahi[mf], bh);
                    mma_tf32(acc[mf][nf], ahi[mf], bl);
                    mma_tf32(acc[mf][nf], alo[mf], bh);
                }
            }
        }

        if (c < NC / KC - 1) {
            float* Ad = sm + (st ^ 1) * STAGEF;
            float* Bd = Ad + 128 * APAD;
            #pragma unroll
            for (int it = 0; it < 4; it++) {
                *(float4*)&Ad[(r0 + 32*it) * APAD + c4] = pa[it];
                *(float4*)&Bd[(r0 + 32*it) * APAD + c4] = pb[it];
            }
        }
        __syncthreads();
    }

    // epilogue: direct float2 stores
    #pragma unroll
    for (int mf = 0; mf < 2; mf++) {
        const int crow = m0 + mrow + mf * 16;
        #pragma unroll
        for (int nf = 0; nf < 8; nf++) {
            const int ccol = (wid >> 2) * 64 + nf * 8 + tig * 2;
            float2 v0 = make_float2(acc[mf][nf][0], acc[mf][nf][1]);
            float2 v1 = make_float2(acc[mf][nf][2], acc[mf][nf][3]);
            *(float2*)&out[(size_t)crow * NH + ccol]       = v0;
            *(float2*)&out[(size_t)(crow + 8) * NH + ccol] = v1;
        }
    }
}

// ===========================================================================
// Flash attention (fp32 FFMA). 64-row q tiles, 64-row k/v tiles.
// P aliases Kt (dead after S-pass) -> smem ~100.5KB -> 2 CTAs/SM.
// Balanced 1D grid: same-SM CTA pairs have complementary causal work.
// ===========================================================================
#define PSTR 68

__global__ __launch_bounds__(256, 2)
void attn_kernel(float* __restrict__ out) {
    extern __shared__ float smf[];
    float* Qt  = smf;                  // [128][PSTR]
    float* Kt  = Qt + 128 * PSTR;      // [128][PSTR]
    float* Vs  = Kt + 128 * PSTR;      // [64][128]
    float* Pt  = Kt;                   // alias: Kt dead after S-pass
    float* m_s = Vs + 64 * NH;         // [64]
    float* l_s = m_s + 64;             // [64]

    const int r_ = (int)blockIdx.x;
    const int d_ = (r_ < 148) ? r_ : (403 - r_);
    const int qtile = 31 - (d_ >> 3);
    const int b     = d_ & 7;
    const int q0    = qtile * 64;

    const int tid  = threadIdx.x;
    const int l16  = tid & 15;
    const int ti   = (tid >> 4) * 4;
    const int tj   = l16 * 4;
    const int tcol = l16 * 8;

    const float* Qg = g_Q + ((size_t)b * NT + q0) * NH;
    #pragma unroll
    for (int it = 0; it < 8; it++) {
        int i  = tid + it * 256;
        int r  = i >> 5;
        int d4 = (i & 31) * 4;
        float4 v = *(const float4*)&Qg[r * NH + d4];
        Qt[(d4+0)*PSTR + r] = v.x;
        Qt[(d4+1)*PSTR + r] = v.y;
        Qt[(d4+2)*PSTR + r] = v.z;
        Qt[(d4+3)*PSTR + r] = v.w;
    }
    if (tid < 64) { m_s[tid] = -INFINITY; l_s[tid] = 0.f; }

    float acc[4][8];
    #pragma unroll
    for (int i = 0; i < 4; i++)
        #pragma unroll
        for (int j = 0; j < 8; j++) acc[i][j] = 0.f;

    const float scale = 0.08838834764831845f;

    for (int kt = 0; kt <= qtile; kt++) {
        const int k0 = kt * 64;
        __syncthreads();
        const float* Kg = g_K + ((size_t)b * NT + k0) * NH;
        const float* Vg = g_V + ((size_t)b * NT + k0) * NH;
        #pragma unroll
        for (int it = 0; it < 8; it++) {
            int i  = tid + it * 256;
            int r  = i >> 5;
            int d4 = (i & 31) * 4;
            float4 v = *(const float4*)&Kg[r * NH + d4];
            Kt[(d4+0)*PSTR + r] = v.x;
            Kt[(d4+1)*PSTR + r] = v.y;
            Kt[(d4+2)*PSTR + r] = v.z;
            Kt[(d4+3)*PSTR + r] = v.w;
            float4 w = *(const float4*)&Vg[r * NH + d4];
            *(float4*)&Vs[r * NH + d4] = w;
        }
        __syncthreads();

        float s[4][4];
        #pragma unroll
        for (int i = 0; i < 4; i++)
            #pragma unroll
            for (int j = 0; j < 4; j++) s[i][j] = 0.f;

        #pragma unroll 8
        for (int d = 0; d < 128; d++) {
            float4 aq = *(const float4*)&Qt[d * PSTR + ti];
            float4 bk = *(const float4*)&Kt[d * PSTR + tj];
            float av[4] = {aq.x, aq.y, aq.z, aq.w};
            float bv[4] = {bk.x, bk.y, bk.z, bk.w};
            #pragma unroll
            for (int i = 0; i < 4; i++)
                #pragma unroll
                for (int j = 0; j < 4; j++)
                    s[i][j] += av[i] * bv[j];
        }

        const bool diag = (kt == qtile);
        float alpha[4];
        #pragma unroll
        for (int ii = 0; ii < 4; ii++) {
            float rmax = -INFINITY;
            #pragma unroll
            for (int jj = 0; jj < 4; jj++) {
                float sv = s[ii][jj] * scale;
                if (diag && (tj + jj > ti + ii)) sv = -INFINITY;
                s[ii][jj] = sv;
                rmax = fmaxf(rmax, sv);
            }
            #pragma unroll
            for (int off = 8; off > 0; off >>= 1)
                rmax = fmaxf(rmax, __shfl_xor_sync(0xffffffffu, rmax, off, 16));
            float mold = m_s[ti + ii];
            float mnew = fmaxf(mold, rmax);
            float a_   = (mold == -INFINITY) ? 0.f : __expf(mold - mnew);
            alpha[ii] = a_;
            float rsum = 0.f;
            #pragma unroll
            for (int jj = 0; jj < 4; jj++) {
                float p = __expf(s[ii][jj] - mnew);
                s[ii][jj] = p;
                rsum += p;
            }
            #pragma unroll
            for (int off = 8; off > 0; off >>= 1)
                rsum += __shfl_xor_sync(0xffffffffu, rsum, off, 16);
            if (l16 == 0) {
                m_s[ti + ii] = mnew;
                l_s[ti + ii] = l_s[ti + ii] * a_ + rsum;
            }
        }

        __syncthreads();   // all Kt reads done before Pt (=Kt) writes
        #pragma unroll
        for (int ii = 0; ii < 4; ii++)
            #pragma unroll
            for (int jj = 0; jj < 4; jj++)
                Pt[(tj + jj) * PSTR + (ti + ii)] = s[ii][jj];

        #pragma unroll
        for (int ii = 0; ii < 4; ii++)
            #pragma unroll
            for (int cc = 0; cc < 8; cc++)
                acc[ii][cc] *= alpha[ii];
        __syncthreads();   // Pt visible

        #pragma unroll 4
        for (int j = 0; j < 64; j++) {
            float4 p4 = *(const float4*)&Pt[j * PSTR + ti];
            float4 v0 = *(const float4*)&Vs[j * NH + tcol];
            float4 v1 = *(const float4*)&Vs[j * NH + tcol + 4];
            float pv[4] = {p4.x, p4.y, p4.z, p4.w};
            float vv[8] = {v0.x, v0.y, v0.z, v0.w, v1.x, v1.y, v1.z, v1.w};
            #pragma unroll
            for (int ii = 0; ii < 4; ii++)
                #pragma unroll
                for (int cc = 0; cc < 8; cc++)
                    acc[ii][cc] += pv[ii] * vv[cc];
        }
    }

    __syncthreads();
    float* Og = out + ((size_t)b * NT + q0) * NH;
    #pragma unroll
    for (int ii = 0; ii < 4; ii++) {
        float inv = 1.f / l_s[ti + ii];
        float4 o0 = make_float4(acc[ii][0]*inv, acc[ii][1]*inv, acc[ii][2]*inv, acc[ii][3]*inv);
        float4 o1 = make_float4(acc[ii][4]*inv, acc[ii][5]*inv, acc[ii][6]*inv, acc[ii][7]*inv);
        *(float4*)&Og[(ti + ii) * NH + tcol]     = o0;
        *(float4*)&Og[(ti + ii) * NH + tcol + 4] = o1;
    }
}

// ---------------------------------------------------------------------------
extern "C" void kernel_launch(void* const* d_in, const int* in_sizes, int n_in,
                              void* d_out, int out_size) {
    const float* x  = (const float*)d_in[0];
    const float* Wq = (const float*)d_in[1];
    const float* Wk = (const float*)d_in[2];
    const float* Wv = (const float*)d_in[3];
    float* out = (float*)d_out;

    cudaFuncSetAttribute(qkv_mma_kernel,
                         cudaFuncAttributeMaxDynamicSharedMemorySize, QKV_SMEM);
    qkv_mma_kernel<<<dim3(NBT / 128, 3), 256, QKV_SMEM>>>(x, Wq, Wk, Wv);

    const int attn_smem = (128 * PSTR * 2 + 64 * NH + 128) * (int)sizeof(float);
    cudaFuncSetAttribute(attn_kernel,
                         cudaFuncAttributeMaxDynamicSharedMemorySize, attn_smem);
    attn_kernel<<<256, 256, attn_smem>>>(out);
}